// round 6
// baseline (speedup 1.0000x reference)
#include <cuda_runtime.h>
#include <cuda_bf16.h>
#include <cstdint>

#define THREADS      256
#define ELEMS        8
#define TILE_FLOATS  (THREADS * ELEMS)      // 2048
#define TILE_BYTES   (TILE_FLOATS * 4)      // 8192

__device__ __forceinline__ float ex2_approx(float v) {
    float r; asm("ex2.approx.f32 %0, %1;" : "=f"(r) : "f"(v)); return r;
}
__device__ __forceinline__ float rcp_approx(float v) {
    float r; asm("rcp.approx.f32 %0, %1;" : "=f"(r) : "f"(v)); return r;
}
__device__ __forceinline__ uint32_t smem_u32(const void* p) {
    uint32_t a;
    asm("{ .reg .u64 t; cvta.to.shared.u64 t, %1; cvt.u32.u64 %0, t; }" : "=r"(a) : "l"(p));
    return a;
}

// Bulk-async streaming quantizer, small-tile / high-occupancy variant:
//   UBLKCP G2S (8KB x tile) -> compute in smem -> UBLKCP S2G (vals, idx).
// 16KB smem/CTA -> 8 CTAs/SM (thread-capped). wait_group.read releases the
// CTA as soon as smem is re-readable instead of waiting for GMEM landing.
__global__ void __launch_bounds__(THREADS) quantizer_kernel(
    const float* __restrict__ x,
    float* __restrict__ out_vals,
    float* __restrict__ out_idx,
    int write_idx)
{
    __shared__ alignas(16) float tv[TILE_FLOATS];   // x in, vals out (in-place)
    __shared__ alignas(16) float ti[TILE_FLOATS];   // idx out
    __shared__ alignas(8)  unsigned long long mbar;

    const int tid = threadIdx.x;
    const size_t gbase = (size_t)blockIdx.x * TILE_FLOATS;

    const uint32_t s_tv = smem_u32(tv);
    const uint32_t s_ti = smem_u32(ti);
    const uint32_t s_mb = smem_u32(&mbar);

    if (tid == 0) {
        asm volatile("mbarrier.init.shared.b64 [%0], %1;" :: "r"(s_mb), "r"(1) : "memory");
        asm volatile("fence.proxy.async.shared::cta;" ::: "memory");
        asm volatile("mbarrier.arrive.expect_tx.shared.b64 _, [%0], %1;"
                     :: "r"(s_mb), "r"((uint32_t)TILE_BYTES) : "memory");
        asm volatile("cp.async.bulk.shared::cta.global.mbarrier::complete_tx::bytes "
                     "[%0], [%1], %2, [%3];"
                     :: "r"(s_tv), "l"(x + gbase), "r"((uint32_t)TILE_BYTES), "r"(s_mb)
                     : "memory");
    }
    __syncthreads();

    // Wait for the tile (parity 0).
    {
        uint32_t done;
        asm volatile(
            "{\n\t.reg .pred p;\n\t"
            "mbarrier.try_wait.parity.acquire.cta.shared::cta.b64 p, [%1], 0;\n\t"
            "selp.b32 %0, 1, 0, p;\n\t}"
            : "=r"(done) : "r"(s_mb) : "memory");
        if (!done) {
            asm volatile(
                "{\n\t.reg .pred P1;\n\t"
                "WL_%=:\n\t"
                "mbarrier.try_wait.parity.acquire.cta.shared::cta.b64 P1, [%0], 0, 0x989680;\n\t"
                "@P1 bra.uni WD_%=;\n\t"
                "bra.uni WL_%=;\n\t"
                "WD_%=:\n\t}"
                :: "r"(s_mb) : "memory");
        }
    }

    const float TWO_LOG2E = 2.8853900817779268f;   // 2*log2(e)
    const float STEP      = 2.0f / 63.0f;

    // Interleaved float4 slots: lane t, chunk j -> slot (j*THREADS + t): 16B
    // apart across lanes -> conflict-free LDS.128/STS.128.
    float4 xv[2];
    #pragma unroll
    for (int j = 0; j < 2; j++)
        xv[j] = reinterpret_cast<const float4*>(tv)[j * THREADS + tid];

    #pragma unroll
    for (int j = 0; j < 2; j++) {
        float vin[4] = {xv[j].x, xv[j].y, xv[j].z, xv[j].w};
        float qv[4], qi[4];
        #pragma unroll
        for (int k = 0; k < 4; k++) {
            float xk = vin[k];
            float ax = fabsf(xk);
            // tanh(|x|) = 1 - 2/(exp(2|x|)+1)
            float e    = ex2_approx(ax * TWO_LOG2E);
            float r    = rcp_approx(e + 1.0f);
            float tmag = fmaf(-2.0f, r, 1.0f);
            float t    = copysignf(tmag, xk);
            // nearest of 64 uniform levels in [-1,1]
            float f  = fmaf(t, 31.5f, 31.5f);
            float cf = rintf(f);
            qv[k] = fmaf(cf, STEP, -1.0f);
            qi[k] = cf;
        }
        reinterpret_cast<float4*>(tv)[j * THREADS + tid] = make_float4(qv[0], qv[1], qv[2], qv[3]);
        reinterpret_cast<float4*>(ti)[j * THREADS + tid] = make_float4(qi[0], qi[1], qi[2], qi[3]);
    }

    __syncthreads();

    if (tid == 0) {
        asm volatile("fence.proxy.async.shared::cta;" ::: "memory");
        asm volatile("cp.async.bulk.global.shared::cta.bulk_group [%0], [%1], %2;"
                     :: "l"(out_vals + gbase), "r"(s_tv), "r"((uint32_t)TILE_BYTES) : "memory");
        if (write_idx) {
            asm volatile("cp.async.bulk.global.shared::cta.bulk_group [%0], [%1], %2;"
                         :: "l"(out_idx + gbase), "r"(s_ti), "r"((uint32_t)TILE_BYTES) : "memory");
        }
        asm volatile("cp.async.bulk.commit_group;" ::: "memory");
        // Only smem-read completion is needed before CTA exit.
        asm volatile("cp.async.bulk.wait_group.read 0;" ::: "memory");
    }
}

extern "C" void kernel_launch(void* const* d_in, const int* in_sizes, int n_in,
                              void* d_out, int out_size) {
    const float* x = (const float*)d_in[0];
    float* out     = (float*)d_out;

    int n = in_sizes[0];            // 4194304 = 2^22
    int write_idx = (out_size >= 2 * n) ? 1 : 0;
    float* out_idx = out + n;

    int blocks = (n + TILE_FLOATS - 1) / TILE_FLOATS;   // 2048

    quantizer_kernel<<<blocks, THREADS>>>(x, out, out_idx, write_idx);
}

// round 7
// speedup vs baseline: 1.0030x; 1.0030x over previous
#include <cuda_runtime.h>
#include <cuda_bf16.h>
#include <cstdint>

#define THREADS      256
#define TILE_FLOATS  2048                    // 8KB per tile
#define TILE_BYTES   (TILE_FLOATS * 4)
#define TILES_PER_CTA 2

__device__ __forceinline__ float ex2_approx(float v) {
    float r; asm("ex2.approx.f32 %0, %1;" : "=f"(r) : "f"(v)); return r;
}
__device__ __forceinline__ float rcp_approx(float v) {
    float r; asm("rcp.approx.f32 %0, %1;" : "=f"(r) : "f"(v)); return r;
}
__device__ __forceinline__ uint32_t smem_u32(const void* p) {
    uint32_t a;
    asm("{ .reg .u64 t; cvta.to.shared.u64 t, %1; cvt.u32.u64 %0, t; }" : "=r"(a) : "l"(p));
    return a;
}

__device__ __forceinline__ void mbar_wait(uint32_t mb) {
    uint32_t done;
    asm volatile(
        "{\n\t.reg .pred p;\n\t"
        "mbarrier.try_wait.parity.acquire.cta.shared::cta.b64 p, [%1], 0;\n\t"
        "selp.b32 %0, 1, 0, p;\n\t}"
        : "=r"(done) : "r"(mb) : "memory");
    if (!done) {
        asm volatile(
            "{\n\t.reg .pred P1;\n\t"
            "WL_%=:\n\t"
            "mbarrier.try_wait.parity.acquire.cta.shared::cta.b64 P1, [%0], 0, 0x989680;\n\t"
            "@P1 bra.uni WD_%=;\n\t"
            "bra.uni WL_%=;\n\t"
            "WD_%=:\n\t}"
            :: "r"(mb) : "memory");
    }
}

// Double-buffered bulk-async quantizer: each CTA owns 2 tiles; both G2S loads
// are front-issued, store(tile0) overlaps compute(tile1). Single wave (1024
// CTAs at 7/SM). Analytic tanh (EX2+RCP) + rint nearest-of-64-uniform-levels.
__global__ void __launch_bounds__(THREADS) quantizer_kernel(
    const float* __restrict__ x,
    float* __restrict__ out_vals,
    float* __restrict__ out_idx,
    int write_idx)
{
    __shared__ alignas(16) float tv[TILES_PER_CTA][TILE_FLOATS];  // x in, vals out
    __shared__ alignas(16) float ti[TILES_PER_CTA][TILE_FLOATS];  // idx out
    __shared__ alignas(8)  unsigned long long mbar[TILES_PER_CTA];

    const int tid = threadIdx.x;
    const size_t gbase = (size_t)blockIdx.x * (TILES_PER_CTA * TILE_FLOATS);

    uint32_t s_tv[TILES_PER_CTA], s_ti[TILES_PER_CTA], s_mb[TILES_PER_CTA];
    #pragma unroll
    for (int s = 0; s < TILES_PER_CTA; s++) {
        s_tv[s] = smem_u32(tv[s]);
        s_ti[s] = smem_u32(ti[s]);
        s_mb[s] = smem_u32(&mbar[s]);
    }

    if (tid == 0) {
        #pragma unroll
        for (int s = 0; s < TILES_PER_CTA; s++)
            asm volatile("mbarrier.init.shared.b64 [%0], %1;" :: "r"(s_mb[s]), "r"(1) : "memory");
        asm volatile("fence.proxy.async.shared::cta;" ::: "memory");
        // Front-issue BOTH tile loads: bulk-level MLP=2, latency exposed once.
        #pragma unroll
        for (int s = 0; s < TILES_PER_CTA; s++) {
            asm volatile("mbarrier.arrive.expect_tx.shared.b64 _, [%0], %1;"
                         :: "r"(s_mb[s]), "r"((uint32_t)TILE_BYTES) : "memory");
            asm volatile("cp.async.bulk.shared::cta.global.mbarrier::complete_tx::bytes "
                         "[%0], [%1], %2, [%3];"
                         :: "r"(s_tv[s]), "l"(x + gbase + s * TILE_FLOATS),
                            "r"((uint32_t)TILE_BYTES), "r"(s_mb[s])
                         : "memory");
        }
    }
    __syncthreads();

    const float TWO_LOG2E = 2.8853900817779268f;   // 2*log2(e)
    const float STEP      = 2.0f / 63.0f;

    #pragma unroll
    for (int s = 0; s < TILES_PER_CTA; s++) {
        mbar_wait(s_mb[s]);

        // Interleaved float4 slots: lane t, chunk j -> slot (j*THREADS + t);
        // consecutive lanes 16B apart -> conflict-free LDS.128/STS.128.
        float4 xv[2];
        #pragma unroll
        for (int j = 0; j < 2; j++)
            xv[j] = reinterpret_cast<const float4*>(tv[s])[j * THREADS + tid];

        #pragma unroll
        for (int j = 0; j < 2; j++) {
            float vin[4] = {xv[j].x, xv[j].y, xv[j].z, xv[j].w};
            float qv[4], qi[4];
            #pragma unroll
            for (int k = 0; k < 4; k++) {
                float xk = vin[k];
                float ax = fabsf(xk);
                // tanh(|x|) = 1 - 2/(exp(2|x|)+1)
                float e    = ex2_approx(ax * TWO_LOG2E);
                float r    = rcp_approx(e + 1.0f);
                float tmag = fmaf(-2.0f, r, 1.0f);
                float t    = copysignf(tmag, xk);
                // nearest of 64 uniform levels in [-1,1]
                float f  = fmaf(t, 31.5f, 31.5f);
                float cf = rintf(f);
                qv[k] = fmaf(cf, STEP, -1.0f);
                qi[k] = cf;
            }
            reinterpret_cast<float4*>(tv[s])[j * THREADS + tid] = make_float4(qv[0], qv[1], qv[2], qv[3]);
            reinterpret_cast<float4*>(ti[s])[j * THREADS + tid] = make_float4(qi[0], qi[1], qi[2], qi[3]);
        }

        __syncthreads();

        if (tid == 0) {
            asm volatile("fence.proxy.async.shared::cta;" ::: "memory");
            asm volatile("cp.async.bulk.global.shared::cta.bulk_group [%0], [%1], %2;"
                         :: "l"(out_vals + gbase + s * TILE_FLOATS), "r"(s_tv[s]),
                            "r"((uint32_t)TILE_BYTES) : "memory");
            if (write_idx) {
                asm volatile("cp.async.bulk.global.shared::cta.bulk_group [%0], [%1], %2;"
                             :: "l"(out_idx + gbase + s * TILE_FLOATS), "r"(s_ti[s]),
                                "r"((uint32_t)TILE_BYTES) : "memory");
            }
            asm volatile("cp.async.bulk.commit_group;" ::: "memory");
        }
        // No wait here: tile s buffers are never reused; store overlaps next tile.
    }

    if (tid == 0) {
        // Only smem-read completion needed before CTA exit.
        asm volatile("cp.async.bulk.wait_group.read 0;" ::: "memory");
    }
}

extern "C" void kernel_launch(void* const* d_in, const int* in_sizes, int n_in,
                              void* d_out, int out_size) {
    const float* x = (const float*)d_in[0];
    float* out     = (float*)d_out;

    int n = in_sizes[0];            // 4194304 = 2^22
    int write_idx = (out_size >= 2 * n) ? 1 : 0;
    float* out_idx = out + n;

    int elems_per_cta = TILES_PER_CTA * TILE_FLOATS;        // 4096
    int blocks = (n + elems_per_cta - 1) / elems_per_cta;   // 1024

    quantizer_kernel<<<blocks, THREADS>>>(x, out, out_idx, write_idx);
}